// round 8
// baseline (speedup 1.0000x reference)
#include <cuda_runtime.h>

// Single-pass inclusive cumsum along leading axis of xs[T, D] (fp32).
// Output: d_out[0:D] = final carry, d_out[D:] = ys[T,D].
//
// Decoupled lookback with CTA-granular flags:
//  - one status flag per (chunk, colgroup): 0 none, 1 agg ready, 2 inclusive
//  - thread 0 walks flags to the nearest inclusive predecessor p*, broadcasts
//  - all threads then sum agg[p*+1..c-1] + inc[p*] with INDEPENDENT loads
// Phase A: per-thread column sum of 32 rows. Phase B: re-read (L2 hot),
// add prefix, stream ys with evict-first stores.

#define THREADS 256
#define C_F4    256            // float4 columns per CTA
#define ROWS    32
#define MAX_CHUNKS 512
#define MAX_SP4    2048
#define MAX_NG     8

static __device__ float4 g_agg4[MAX_CHUNKS * MAX_SP4];
static __device__ float4 g_inc4[MAX_CHUNKS * MAX_SP4];
static __device__ int    g_flag[MAX_CHUNKS * MAX_NG];

__device__ __forceinline__ int ld_acquire(const int* p) {
    int v;
    asm volatile("ld.acquire.gpu.global.b32 %0, [%1];" : "=r"(v) : "l"(p) : "memory");
    return v;
}
__device__ __forceinline__ void st_release(int* p, int v) {
    asm volatile("st.release.gpu.global.b32 [%0], %1;" :: "l"(p), "r"(v) : "memory");
}
__device__ __forceinline__ float4 f4add(float4 a, float4 b) {
    return make_float4(a.x + b.x, a.y + b.y, a.z + b.z, a.w + b.w);
}

__global__ __launch_bounds__(THREADS)
void scan_lookback(const float4* __restrict__ xs4, float4* __restrict__ ys4,
                   float4* __restrict__ carry4,
                   int stride4, int sp4, int T, int chunks, int ng, int rows) {
    __shared__ int sh_pstar;

    const int g   = blockIdx.x;            // column group
    const int c   = blockIdx.y;            // chunk (x fastest in bid order)
    const int t4  = threadIdx.x;
    const int gc4 = g * C_F4 + t4;
    const bool act = gc4 < stride4;

    const int row0 = c * rows;
    const int nr   = min(rows, T - row0);
    const float4* xp = xs4 + (size_t)row0 * stride4 + gc4;

    // ---- Phase A: aggregate this chunk's column ----
    float4 agg = make_float4(0.f, 0.f, 0.f, 0.f);
    if (act) {
        if (nr == ROWS) {
#pragma unroll
            for (int r = 0; r < ROWS; ++r)
                agg = f4add(agg, __ldg(xp + (size_t)r * stride4));
        } else {
            for (int r = 0; r < nr; ++r)
                agg = f4add(agg, __ldg(xp + (size_t)r * stride4));
        }
    }

    const size_t lane = (size_t)c * sp4 + gc4;
    int* flag_c = &g_flag[(size_t)c * ng + g];

    float4 ex = make_float4(0.f, 0.f, 0.f, 0.f);

    if (c == 0) {
        if (act) g_inc4[lane] = agg;
        __syncthreads();
        if (threadIdx.x == 0) st_release(flag_c, 2);
    } else {
        // publish aggregate
        if (act) g_agg4[lane] = agg;
        __syncthreads();
        if (threadIdx.x == 0) st_release(flag_c, 1);

        // thread 0 walks to nearest inclusive predecessor
        if (threadIdx.x == 0) {
            int p = c - 1;
            for (;;) {
                int s = ld_acquire(&g_flag[(size_t)p * ng + g]);
                if (s == 2) break;
                if (s == 1) { --p; continue; }
                __nanosleep(32);
            }
            sh_pstar = p;
        }
        __syncthreads();
        const int pstar = sh_pstar;

        // independent payload loads: inc[pstar] + aggs (pstar, c)
        if (act) {
            ex = g_inc4[(size_t)pstar * sp4 + gc4];
            int p = pstar + 1;
            for (; p + 4 <= c; p += 4) {
                float4 a0 = g_agg4[(size_t)(p + 0) * sp4 + gc4];
                float4 a1 = g_agg4[(size_t)(p + 1) * sp4 + gc4];
                float4 a2 = g_agg4[(size_t)(p + 2) * sp4 + gc4];
                float4 a3 = g_agg4[(size_t)(p + 3) * sp4 + gc4];
                ex = f4add(ex, f4add(f4add(a0, a1), f4add(a2, a3)));
            }
            for (; p < c; ++p)
                ex = f4add(ex, g_agg4[(size_t)p * sp4 + gc4]);
            g_inc4[lane] = f4add(ex, agg);
        }
        __syncthreads();
        if (threadIdx.x == 0) st_release(flag_c, 2);
    }

    if (act && c == chunks - 1)
        carry4[gc4] = f4add(ex, agg);       // final carry

    // ---- Phase B: re-read tile (L2 hot), accumulate, stream out ----
    if (act) {
        float4* yp = ys4 + (size_t)row0 * stride4 + gc4;
        float4 acc = ex;
        if (nr == ROWS) {
#pragma unroll 8
            for (int r = 0; r < ROWS; ++r) {
                float4 v = __ldcs(xp + (size_t)r * stride4);
                acc = f4add(acc, v);
                __stcs(yp + (size_t)r * stride4, acc);
            }
        } else {
            for (int r = 0; r < nr; ++r) {
                float4 v = __ldcs(xp + (size_t)r * stride4);
                acc = f4add(acc, v);
                __stcs(yp + (size_t)r * stride4, acc);
            }
        }
    }
}

// ---------------------------------------------------------------------------
extern "C" void kernel_launch(void* const* d_in, const int* in_sizes, int n_in,
                              void* d_out, int out_size) {
    const float* xs = (const float*)d_in[0];
    float* out = (float*)d_out;

    const int total = in_sizes[0];          // T * D
    int D = out_size - total;
    if (D <= 0 || total % D != 0) D = 4096;
    const int T = total / D;

    const int stride4 = D / 4;
    int ng = (stride4 + C_F4 - 1) / C_F4;
    if (ng > MAX_NG) ng = MAX_NG;           // (dataset: ng = 4)
    const int sp4 = ng * C_F4;

    int rows = ROWS;
    int chunks = (T + rows - 1) / rows;
    while (chunks > MAX_CHUNKS) { rows <<= 1; chunks = (T + rows - 1) / rows; }

    float* carry = out;
    float* ys    = out + D;

    void* flag_ptr = nullptr;
    cudaGetSymbolAddress(&flag_ptr, g_flag);
    cudaMemsetAsync(flag_ptr, 0, (size_t)chunks * ng * sizeof(int));

    dim3 grid(ng, chunks);
    scan_lookback<<<grid, THREADS>>>((const float4*)xs, (float4*)ys,
                                     (float4*)carry, stride4, sp4, T,
                                     chunks, ng, rows);
}

// round 9
// speedup vs baseline: 1.3421x; 1.3421x over previous
#include <cuda_runtime.h>

// Single-pass inclusive cumsum along leading axis of xs[T, D] (fp32).
// Output: d_out[0:D] = final carry, d_out[D:] = ys[T,D].
//
// Decoupled lookback, per-column flags (R7 protocol), ROWS=64:
//  - 512 CTAs (one resident wave), chunks=128 -> short inc chain
//  - phase A: per-thread column sum of 64 rows (fills L2)
//  - per-column acquire/release lookback
//  - phase B: re-read tile (L2 hot), add prefix, stream ys (evict-first)

#define THREADS 256
#define C_F4    256            // float4 columns per CTA
#define ROWS    64             // rows per chunk
#define MAX_CHUNKS 256
#define MAX_SP4    2048

static __device__ float4 g_agg4[MAX_CHUNKS * MAX_SP4];
static __device__ float4 g_inc4[MAX_CHUNKS * MAX_SP4];
static __device__ int    g_stat[MAX_CHUNKS * MAX_SP4];  // 0 none, 1 agg, 2 inclusive

__device__ __forceinline__ int ld_acquire(const int* p) {
    int v;
    asm volatile("ld.acquire.gpu.global.b32 %0, [%1];" : "=r"(v) : "l"(p) : "memory");
    return v;
}
__device__ __forceinline__ void st_release(int* p, int v) {
    asm volatile("st.release.gpu.global.b32 [%0], %1;" :: "l"(p), "r"(v) : "memory");
}
__device__ __forceinline__ float4 f4add(float4 a, float4 b) {
    return make_float4(a.x + b.x, a.y + b.y, a.z + b.z, a.w + b.w);
}

__global__ __launch_bounds__(THREADS)
void scan_lookback(const float4* __restrict__ xs4, float4* __restrict__ ys4,
                   float4* __restrict__ carry4,
                   int stride4, int sp4, int T, int chunks, int rows) {
    const int g   = blockIdx.x;            // column group
    const int c   = blockIdx.y;            // chunk (x fastest in bid order)
    const int t4  = threadIdx.x;
    const int gc4 = g * C_F4 + t4;
    if (gc4 >= stride4) return;

    const int row0 = c * rows;
    const int nr   = min(rows, T - row0);
    const float4* xp = xs4 + (size_t)row0 * stride4 + gc4;

    // ---- Phase A: aggregate this chunk's column (fills L2) ----
    float4 agg = make_float4(0.f, 0.f, 0.f, 0.f);
    {
        int r = 0;
        for (; r + 8 <= nr; r += 8) {
            float4 v0 = __ldg(xp + (size_t)(r + 0) * stride4);
            float4 v1 = __ldg(xp + (size_t)(r + 1) * stride4);
            float4 v2 = __ldg(xp + (size_t)(r + 2) * stride4);
            float4 v3 = __ldg(xp + (size_t)(r + 3) * stride4);
            float4 v4 = __ldg(xp + (size_t)(r + 4) * stride4);
            float4 v5 = __ldg(xp + (size_t)(r + 5) * stride4);
            float4 v6 = __ldg(xp + (size_t)(r + 6) * stride4);
            float4 v7 = __ldg(xp + (size_t)(r + 7) * stride4);
            agg = f4add(agg, f4add(f4add(v0, v1), f4add(v2, v3)));
            agg = f4add(agg, f4add(f4add(v4, v5), f4add(v6, v7)));
        }
        for (; r < nr; ++r) agg = f4add(agg, __ldg(xp + (size_t)r * stride4));
    }

    // ---- Publish + per-column lookback ----
    const size_t lane = (size_t)c * sp4 + gc4;
    float4 ex = make_float4(0.f, 0.f, 0.f, 0.f);
    if (c == 0) {
        g_inc4[lane] = agg;
        st_release(&g_stat[lane], 2);
    } else {
        g_agg4[lane] = agg;
        st_release(&g_stat[lane], 1);
        int p = c - 1;
        for (;;) {
            const size_t pl = (size_t)p * sp4 + gc4;
            int s = ld_acquire(&g_stat[pl]);
            while (s == 0) { __nanosleep(32); s = ld_acquire(&g_stat[pl]); }
            ex = f4add(ex, (s == 2) ? g_inc4[pl] : g_agg4[pl]);
            if (s == 2) break;
            --p;
        }
        g_inc4[lane] = f4add(ex, agg);
        st_release(&g_stat[lane], 2);
    }
    if (c == chunks - 1)
        carry4[gc4] = f4add(ex, agg);       // final carry

    // ---- Phase B: re-read tile (L2 hot), accumulate, stream out ----
    float4* yp = ys4 + (size_t)row0 * stride4 + gc4;
    float4 acc = ex;
    {
        int r = 0;
        for (; r + 8 <= nr; r += 8) {
            float4 v0 = __ldcs(xp + (size_t)(r + 0) * stride4);
            float4 v1 = __ldcs(xp + (size_t)(r + 1) * stride4);
            float4 v2 = __ldcs(xp + (size_t)(r + 2) * stride4);
            float4 v3 = __ldcs(xp + (size_t)(r + 3) * stride4);
            float4 v4 = __ldcs(xp + (size_t)(r + 4) * stride4);
            float4 v5 = __ldcs(xp + (size_t)(r + 5) * stride4);
            float4 v6 = __ldcs(xp + (size_t)(r + 6) * stride4);
            float4 v7 = __ldcs(xp + (size_t)(r + 7) * stride4);
            acc = f4add(acc, v0); __stcs(yp + (size_t)(r + 0) * stride4, acc);
            acc = f4add(acc, v1); __stcs(yp + (size_t)(r + 1) * stride4, acc);
            acc = f4add(acc, v2); __stcs(yp + (size_t)(r + 2) * stride4, acc);
            acc = f4add(acc, v3); __stcs(yp + (size_t)(r + 3) * stride4, acc);
            acc = f4add(acc, v4); __stcs(yp + (size_t)(r + 4) * stride4, acc);
            acc = f4add(acc, v5); __stcs(yp + (size_t)(r + 5) * stride4, acc);
            acc = f4add(acc, v6); __stcs(yp + (size_t)(r + 6) * stride4, acc);
            acc = f4add(acc, v7); __stcs(yp + (size_t)(r + 7) * stride4, acc);
        }
        for (; r < nr; ++r) {
            float4 v = __ldcs(xp + (size_t)r * stride4);
            acc = f4add(acc, v);
            __stcs(yp + (size_t)r * stride4, acc);
        }
    }
}

// ---------------------------------------------------------------------------
extern "C" void kernel_launch(void* const* d_in, const int* in_sizes, int n_in,
                              void* d_out, int out_size) {
    const float* xs = (const float*)d_in[0];
    float* out = (float*)d_out;

    const int total = in_sizes[0];          // T * D
    int D = out_size - total;
    if (D <= 0 || total % D != 0) D = 4096;
    const int T = total / D;

    const int stride4 = D / 4;
    const int ngroups = (stride4 + C_F4 - 1) / C_F4;
    const int sp4     = ngroups * C_F4;

    int rows = ROWS;
    int chunks = (T + rows - 1) / rows;
    while (chunks > MAX_CHUNKS) { rows <<= 1; chunks = (T + rows - 1) / rows; }

    float* carry = out;
    float* ys    = out + D;

    void* stat_ptr = nullptr;
    cudaGetSymbolAddress(&stat_ptr, g_stat);
    cudaMemsetAsync(stat_ptr, 0, (size_t)chunks * sp4 * sizeof(int));

    dim3 grid(ngroups, chunks);
    scan_lookback<<<grid, THREADS>>>((const float4*)xs, (float4*)ys,
                                     (float4*)carry, stride4, sp4, T,
                                     chunks, rows);
}

// round 10
// speedup vs baseline: 1.3608x; 1.0140x over previous
#include <cuda_runtime.h>

// Single-pass inclusive cumsum along leading axis of xs[T, D] (fp32).
// Output: d_out[0:D] = final carry, d_out[D:] = ys[T,D].
//
// Decoupled lookback, per-column flags, ROWS=64 (R9 structure), plus:
// phase-A loads carry an L2::evict_last cache policy so xs stays resident
// in L2 for the phase-B re-read (evict-first), cutting DRAM re-read misses.

#define THREADS 256
#define C_F4    256            // float4 columns per CTA
#define ROWS    64             // rows per chunk
#define MAX_CHUNKS 256
#define MAX_SP4    2048

static __device__ float4 g_agg4[MAX_CHUNKS * MAX_SP4];
static __device__ float4 g_inc4[MAX_CHUNKS * MAX_SP4];
static __device__ int    g_stat[MAX_CHUNKS * MAX_SP4];  // 0 none, 1 agg, 2 inclusive

__device__ __forceinline__ unsigned long long mk_policy_keep() {
    unsigned long long pol;
    asm("createpolicy.fractional.L2::evict_last.b64 %0, 1.0;" : "=l"(pol));
    return pol;
}
__device__ __forceinline__ float4 ldg_keep(const float4* p, unsigned long long pol) {
    float4 v;
    asm volatile("ld.global.L2::cache_hint.v4.f32 {%0,%1,%2,%3}, [%4], %5;"
                 : "=f"(v.x), "=f"(v.y), "=f"(v.z), "=f"(v.w)
                 : "l"(p), "l"(pol));
    return v;
}
__device__ __forceinline__ int ld_acquire(const int* p) {
    int v;
    asm volatile("ld.acquire.gpu.global.b32 %0, [%1];" : "=r"(v) : "l"(p) : "memory");
    return v;
}
__device__ __forceinline__ void st_release(int* p, int v) {
    asm volatile("st.release.gpu.global.b32 [%0], %1;" :: "l"(p), "r"(v) : "memory");
}
__device__ __forceinline__ float4 f4add(float4 a, float4 b) {
    return make_float4(a.x + b.x, a.y + b.y, a.z + b.z, a.w + b.w);
}

__global__ __launch_bounds__(THREADS)
void scan_lookback(const float4* __restrict__ xs4, float4* __restrict__ ys4,
                   float4* __restrict__ carry4,
                   int stride4, int sp4, int T, int chunks, int rows) {
    const int g   = blockIdx.x;            // column group
    const int c   = blockIdx.y;            // chunk (x fastest in bid order)
    const int t4  = threadIdx.x;
    const int gc4 = g * C_F4 + t4;
    if (gc4 >= stride4) return;

    const int row0 = c * rows;
    const int nr   = min(rows, T - row0);
    const float4* xp = xs4 + (size_t)row0 * stride4 + gc4;
    const unsigned long long pol = mk_policy_keep();

    // ---- Phase A: aggregate this chunk's column, pinning xs in L2 ----
    float4 agg = make_float4(0.f, 0.f, 0.f, 0.f);
    {
        int r = 0;
        for (; r + 8 <= nr; r += 8) {
            float4 v0 = ldg_keep(xp + (size_t)(r + 0) * stride4, pol);
            float4 v1 = ldg_keep(xp + (size_t)(r + 1) * stride4, pol);
            float4 v2 = ldg_keep(xp + (size_t)(r + 2) * stride4, pol);
            float4 v3 = ldg_keep(xp + (size_t)(r + 3) * stride4, pol);
            float4 v4 = ldg_keep(xp + (size_t)(r + 4) * stride4, pol);
            float4 v5 = ldg_keep(xp + (size_t)(r + 5) * stride4, pol);
            float4 v6 = ldg_keep(xp + (size_t)(r + 6) * stride4, pol);
            float4 v7 = ldg_keep(xp + (size_t)(r + 7) * stride4, pol);
            agg = f4add(agg, f4add(f4add(v0, v1), f4add(v2, v3)));
            agg = f4add(agg, f4add(f4add(v4, v5), f4add(v6, v7)));
        }
        for (; r < nr; ++r) agg = f4add(agg, ldg_keep(xp + (size_t)r * stride4, pol));
    }

    // ---- Publish + per-column lookback ----
    const size_t lane = (size_t)c * sp4 + gc4;
    float4 ex = make_float4(0.f, 0.f, 0.f, 0.f);
    if (c == 0) {
        g_inc4[lane] = agg;
        st_release(&g_stat[lane], 2);
    } else {
        g_agg4[lane] = agg;
        st_release(&g_stat[lane], 1);
        int p = c - 1;
        for (;;) {
            const size_t pl = (size_t)p * sp4 + gc4;
            int s = ld_acquire(&g_stat[pl]);
            while (s == 0) { __nanosleep(32); s = ld_acquire(&g_stat[pl]); }
            ex = f4add(ex, (s == 2) ? g_inc4[pl] : g_agg4[pl]);
            if (s == 2) break;
            --p;
        }
        g_inc4[lane] = f4add(ex, agg);
        st_release(&g_stat[lane], 2);
    }
    if (c == chunks - 1)
        carry4[gc4] = f4add(ex, agg);       // final carry

    // ---- Phase B: re-read tile (L2 pinned -> hits), accumulate, stream out ----
    float4* yp = ys4 + (size_t)row0 * stride4 + gc4;
    float4 acc = ex;
    {
        int r = 0;
        for (; r + 8 <= nr; r += 8) {
            float4 v0 = __ldcs(xp + (size_t)(r + 0) * stride4);
            float4 v1 = __ldcs(xp + (size_t)(r + 1) * stride4);
            float4 v2 = __ldcs(xp + (size_t)(r + 2) * stride4);
            float4 v3 = __ldcs(xp + (size_t)(r + 3) * stride4);
            float4 v4 = __ldcs(xp + (size_t)(r + 4) * stride4);
            float4 v5 = __ldcs(xp + (size_t)(r + 5) * stride4);
            float4 v6 = __ldcs(xp + (size_t)(r + 6) * stride4);
            float4 v7 = __ldcs(xp + (size_t)(r + 7) * stride4);
            acc = f4add(acc, v0); __stcs(yp + (size_t)(r + 0) * stride4, acc);
            acc = f4add(acc, v1); __stcs(yp + (size_t)(r + 1) * stride4, acc);
            acc = f4add(acc, v2); __stcs(yp + (size_t)(r + 2) * stride4, acc);
            acc = f4add(acc, v3); __stcs(yp + (size_t)(r + 3) * stride4, acc);
            acc = f4add(acc, v4); __stcs(yp + (size_t)(r + 4) * stride4, acc);
            acc = f4add(acc, v5); __stcs(yp + (size_t)(r + 5) * stride4, acc);
            acc = f4add(acc, v6); __stcs(yp + (size_t)(r + 6) * stride4, acc);
            acc = f4add(acc, v7); __stcs(yp + (size_t)(r + 7) * stride4, acc);
        }
        for (; r < nr; ++r) {
            float4 v = __ldcs(xp + (size_t)r * stride4);
            acc = f4add(acc, v);
            __stcs(yp + (size_t)r * stride4, acc);
        }
    }
}

// ---------------------------------------------------------------------------
extern "C" void kernel_launch(void* const* d_in, const int* in_sizes, int n_in,
                              void* d_out, int out_size) {
    const float* xs = (const float*)d_in[0];
    float* out = (float*)d_out;

    const int total = in_sizes[0];          // T * D
    int D = out_size - total;
    if (D <= 0 || total % D != 0) D = 4096;
    const int T = total / D;

    const int stride4 = D / 4;
    const int ngroups = (stride4 + C_F4 - 1) / C_F4;
    const int sp4     = ngroups * C_F4;

    int rows = ROWS;
    int chunks = (T + rows - 1) / rows;
    while (chunks > MAX_CHUNKS) { rows <<= 1; chunks = (T + rows - 1) / rows; }

    float* carry = out;
    float* ys    = out + D;

    void* stat_ptr = nullptr;
    cudaGetSymbolAddress(&stat_ptr, g_stat);
    cudaMemsetAsync(stat_ptr, 0, (size_t)chunks * sp4 * sizeof(int));

    dim3 grid(ngroups, chunks);
    scan_lookback<<<grid, THREADS>>>((const float4*)xs, (float4*)ys,
                                     (float4*)carry, stride4, sp4, T,
                                     chunks, rows);
}